// round 1
// baseline (speedup 1.0000x reference)
#include <cuda_runtime.h>
#include <cuda_bf16.h>
#include <math.h>

// Problem constants
#define BATCH   64
#define FRAMES  128
#define N_IN    512
#define N_HID   2048
#define TP1     129            // FRAMES + 1
// per-array output elements: 2 layers * 64 * 129 * 2048
#define ARR_ELEMS (2u * 64u * 129u * 2048u)

// Tile config
#define BM 64     // all batches
#define BN 32     // column tile
#define BK 16
#define NTHREADS 128

// ---------------------------------------------------------------------------
// Init kernel: write t=0 slices (mems = mem0, spikes = 0)
// ---------------------------------------------------------------------------
__global__ void init_kernel(const float* __restrict__ m01,
                            const float* __restrict__ m02,
                            float* __restrict__ mems,
                            float* __restrict__ spikes)
{
    int idx = blockIdx.x * blockDim.x + threadIdx.x;   // 0 .. 2*64*2048-1
    int total = 2 * BATCH * N_HID;
    if (idx >= total) return;
    int l = idx / (BATCH * N_HID);
    int r = idx - l * (BATCH * N_HID);
    int b = r / N_HID;
    int h = r - b * N_HID;
    const float* m0 = l ? m02 : m01;
    size_t o = (((size_t)l * BATCH + b) * TP1 + 0) * N_HID + h;
    mems[o]   = m0[(size_t)b * N_HID + h];
    spikes[o] = 0.0f;
}

// ---------------------------------------------------------------------------
// Step kernel: output time index tt (1..128).
//   z  = s_prev @ A          (K = 2048)
//   u  = x[:,tt-1,:] @ W     (K = 512)
//   y  = tanh(0.5*(z + u) + 0.5*bias)
//   m  = 0.5*m_prev - 0.5*(1 - s_prev) + y ;  s = (m > 0.5)
// Grid: (64 col tiles, 2 layers), 128 threads. BM=64, BN=32, BK=16, 4x4/thread.
// ---------------------------------------------------------------------------
__global__ void __launch_bounds__(NTHREADS)
step_kernel(const float* __restrict__ x,
            const float* __restrict__ W1, const float* __restrict__ A1, const float* __restrict__ b1,
            const float* __restrict__ W2, const float* __restrict__ A2, const float* __restrict__ b2,
            float* __restrict__ mems, float* __restrict__ spikes, int tt)
{
    const int l  = blockIdx.y;
    const int c0 = blockIdx.x * BN;

    const float* __restrict__ A    = l ? A2 : A1;
    const float* __restrict__ W    = l ? W2 : W1;
    const float* __restrict__ bias = l ? b2 : b1;

    __shared__ float sS[BK][BM + 4];   // +4 pad: avoids STS bank conflicts, keeps 16B align
    __shared__ float sA[BK][BN];

    const int tid  = threadIdx.x;
    const int m_id = tid >> 3;   // 0..15  (batch group)
    const int n_id = tid & 7;    // 0..7   (col group)
    const int bb   = m_id * 4;
    const int cc   = n_id * 4;

    float acc[4][4];
#pragma unroll
    for (int i = 0; i < 4; i++)
#pragma unroll
        for (int j = 0; j < 4; j++) acc[i][j] = 0.0f;

    // Operand bases
    const size_t lay_off = (size_t)l * BATCH * TP1 * N_HID;
    const float* Sprev = spikes + lay_off + (size_t)(tt - 1) * N_HID; // + b*TP1*N_HID + k
    const float* Xrow  = x + (size_t)(tt - 1) * N_IN;                 // + b*FRAMES*N_IN + n

    // -------- Phase 1: s_prev @ A, K = N_HID --------
    for (int k0 = 0; k0 < N_HID; k0 += BK) {
#pragma unroll
        for (int e = 0; e < 8; e++) {
            int idx = tid + e * NTHREADS;       // 0..1023
            int b = idx >> 4;                   // row
            int k = idx & 15;                   // 16 consecutive k per row (coalesced 64B)
            sS[k][b] = Sprev[(size_t)b * (TP1 * N_HID) + (k0 + k)];
        }
#pragma unroll
        for (int e = 0; e < 4; e++) {
            int idx = tid + e * NTHREADS;       // 0..511
            int k = idx >> 5;
            int c = idx & 31;                   // 32 consecutive cols (coalesced)
            sA[k][c] = A[(size_t)(k0 + k) * N_HID + (c0 + c)];
        }
        __syncthreads();
#pragma unroll
        for (int k = 0; k < BK; k++) {
            float4 sv = *reinterpret_cast<const float4*>(&sS[k][bb]);
            float4 av = *reinterpret_cast<const float4*>(&sA[k][cc]);
            float s4[4] = {sv.x, sv.y, sv.z, sv.w};
            float a4[4] = {av.x, av.y, av.z, av.w};
#pragma unroll
            for (int i = 0; i < 4; i++)
#pragma unroll
                for (int j = 0; j < 4; j++) acc[i][j] += s4[i] * a4[j];
        }
        __syncthreads();
    }

    // -------- Phase 2: x_t @ W, K = N_IN --------
    for (int k0 = 0; k0 < N_IN; k0 += BK) {
#pragma unroll
        for (int e = 0; e < 8; e++) {
            int idx = tid + e * NTHREADS;
            int b = idx >> 4;
            int k = idx & 15;
            sS[k][b] = Xrow[(size_t)b * (FRAMES * N_IN) + (k0 + k)];
        }
#pragma unroll
        for (int e = 0; e < 4; e++) {
            int idx = tid + e * NTHREADS;
            int k = idx >> 5;
            int c = idx & 31;
            sA[k][c] = W[(size_t)(k0 + k) * N_HID + (c0 + c)];
        }
        __syncthreads();
#pragma unroll
        for (int k = 0; k < BK; k++) {
            float4 sv = *reinterpret_cast<const float4*>(&sS[k][bb]);
            float4 av = *reinterpret_cast<const float4*>(&sA[k][cc]);
            float s4[4] = {sv.x, sv.y, sv.z, sv.w};
            float a4[4] = {av.x, av.y, av.z, av.w};
#pragma unroll
            for (int i = 0; i < 4; i++)
#pragma unroll
                for (int j = 0; j < 4; j++) acc[i][j] += s4[i] * a4[j];
        }
        __syncthreads();
    }

    // -------- Epilogue: LIF update, write t = tt --------
#pragma unroll
    for (int i = 0; i < 4; i++) {
        int b = bb + i;
        size_t rowPrev = lay_off + ((size_t)b * TP1 + (tt - 1)) * N_HID;
        size_t rowCur  = lay_off + ((size_t)b * TP1 + tt) * N_HID;
#pragma unroll
        for (int j = 0; j < 4; j++) {
            int c = c0 + cc + j;
            float pre = 0.5f * acc[i][j] + 0.5f * bias[c];
            float y   = tanhf(pre);
            float sp  = spikes[rowPrev + c];
            float mp  = mems[rowPrev + c];
            float mn  = mp * 0.5f - 0.5f * (1.0f - sp) + y;
            mems[rowCur + c]   = mn;
            spikes[rowCur + c] = (mn > 0.5f) ? 1.0f : 0.0f;
        }
    }
}

// ---------------------------------------------------------------------------
// Launch
// ---------------------------------------------------------------------------
extern "C" void kernel_launch(void* const* d_in, const int* in_sizes, int n_in,
                              void* d_out, int out_size)
{
    const float* x   = (const float*)d_in[0];
    const float* W1  = (const float*)d_in[1];
    const float* A1  = (const float*)d_in[2];
    const float* b1  = (const float*)d_in[3];
    const float* W2  = (const float*)d_in[4];
    const float* A2  = (const float*)d_in[5];
    const float* b2  = (const float*)d_in[6];
    const float* m01 = (const float*)d_in[7];
    const float* m02 = (const float*)d_in[8];

    float* mems   = (float*)d_out;
    float* spikes = mems + (size_t)(out_size / 2);   // second half of concatenated output

    {
        int total = 2 * BATCH * N_HID;
        int threads = 256;
        int blocks = (total + threads - 1) / threads;
        init_kernel<<<blocks, threads>>>(m01, m02, mems, spikes);
    }

    dim3 grid(N_HID / BN, 2);   // 64 col tiles x 2 layers = 128 blocks
    for (int tt = 1; tt <= FRAMES; tt++) {
        step_kernel<<<grid, NTHREADS>>>(x, W1, A1, b1, W2, A2, b2, mems, spikes, tt);
    }
}

// round 10
// speedup vs baseline: 1.6296x; 1.6296x over previous
#include <cuda_runtime.h>
#include <cuda_bf16.h>
#include <math.h>
#include <stdint.h>

// Problem constants
#define NL     2
#define BATCH  64
#define FRAMES 128
#define NIN    512
#define H      2048
#define TP1    129

#define KA   (3 * H)          // step GEMM K (A hi|lo|lolo)     = 6144
#define KW   (6 * NIN)        // U GEMM K (6 x/W product blocks) = 3072

// Step tiling: 64x32 block, 8 warps = 2m x 2n x 2k(split-K)
#define BM     64
#define BN     32
#define BK     64
#define NIT    (KA / BK)      // 96
#define NTH    256
#define STAGES 3
#define SSTR   72             // padded smem row stride (bf16): conflict-free LDSM

// U-precompute tiling: 64x64 block, 4 warps m32n32, 2-stage pipeline
#define PBM    64
#define PBN    64
#define PBK    64
#define PNIT   (KW / PBK)     // 48
#define PSTR   72

// ---------------------------------------------------------------------------
// Scratch (device globals)
// ---------------------------------------------------------------------------
__device__ __nv_bfloat16 g_Acat[NL][H][KA];               // [l][n][k] ~50 MB
__device__ __nv_bfloat16 g_Wcat[NL][H][KW];               // [l][n][k] ~25 MB
__device__ __nv_bfloat16 g_xcat[BATCH * FRAMES][3 * NIN]; // row=t*64+b ~25 MB
__device__ __nv_bfloat16 g_sbf[2][NL][BATCH][H];          // ping-pong spikes
__device__ float         g_U[NL][FRAMES * BATCH][H];      // U = xW + b, fp32 ~134 MB

// ---------------------------------------------------------------------------
// Helpers
// ---------------------------------------------------------------------------
__device__ __forceinline__ void cpasync16(void* s, const void* g) {
    uint32_t sa = (uint32_t)__cvta_generic_to_shared(s);
    asm volatile("cp.async.cg.shared.global [%0], [%1], 16;\n" :: "r"(sa), "l"(g));
}
__device__ __forceinline__ void cp_commit() {
    asm volatile("cp.async.commit_group;\n" ::: "memory");
}
__device__ __forceinline__ void cp_wait1() {
    asm volatile("cp.async.wait_group 1;\n" ::: "memory");
}
__device__ __forceinline__ void ldsm4(uint32_t* r, const __nv_bfloat16* p) {
    uint32_t a = (uint32_t)__cvta_generic_to_shared(p);
    asm volatile("ldmatrix.sync.aligned.m8n8.x4.shared.b16 {%0,%1,%2,%3},[%4];"
                 : "=r"(r[0]), "=r"(r[1]), "=r"(r[2]), "=r"(r[3]) : "r"(a));
}
__device__ __forceinline__ void mma16816(float* c, const uint32_t* a, uint32_t b0, uint32_t b1) {
    asm volatile("mma.sync.aligned.m16n8k16.row.col.f32.bf16.bf16.f32 "
                 "{%0,%1,%2,%3},{%4,%5,%6,%7},{%8,%9},{%0,%1,%2,%3};"
                 : "+f"(c[0]), "+f"(c[1]), "+f"(c[2]), "+f"(c[3])
                 : "r"(a[0]), "r"(a[1]), "r"(a[2]), "r"(a[3]), "r"(b0), "r"(b1));
}
__device__ __forceinline__ void split3(float a, __nv_bfloat16& h, __nv_bfloat16& lo, __nv_bfloat16& ll) {
    h = __float2bfloat16(a);
    float r1 = a - __bfloat162float(h);
    lo = __float2bfloat16(r1);
    float r2 = r1 - __bfloat162float(lo);
    ll = __float2bfloat16(r2);
}

// ---------------------------------------------------------------------------
// Init: t=0 output slices + zero spike scratch (parity 0)
// ---------------------------------------------------------------------------
__global__ void init_kernel(const float* __restrict__ m01,
                            const float* __restrict__ m02,
                            float* __restrict__ mems,
                            float* __restrict__ spikes)
{
    int idx = blockIdx.x * blockDim.x + threadIdx.x;
    int total = NL * BATCH * H;
    if (idx >= total) return;
    int l = idx / (BATCH * H);
    int r = idx - l * (BATCH * H);
    int b = r / H;
    int h = r - b * H;
    const float* m0 = l ? m02 : m01;
    size_t o = (((size_t)l * BATCH + b) * TP1 + 0) * H + h;
    mems[o]   = m0[(size_t)b * H + h];
    spikes[o] = 0.0f;
    g_sbf[0][l][b][h] = __float2bfloat16(0.0f);
}

// ---------------------------------------------------------------------------
// Convert A: [k][n] fp32 -> [n][k] bf16 {hi, lo, lolo} at k, k+2048, k+4096
// ---------------------------------------------------------------------------
__global__ void convA_kernel(const float* __restrict__ A1, const float* __restrict__ A2)
{
    int l = blockIdx.z;
    const float* __restrict__ A = l ? A2 : A1;
    __shared__ float t[32][33];
    int k0 = blockIdx.x * 32, n0 = blockIdx.y * 32;
    for (int i = threadIdx.y; i < 32; i += 8)
        t[i][threadIdx.x] = A[(size_t)(k0 + i) * H + n0 + threadIdx.x];
    __syncthreads();
    for (int i = threadIdx.y; i < 32; i += 8) {
        float a = t[threadIdx.x][i];
        __nv_bfloat16 h, lo, ll;
        split3(a, h, lo, ll);
        __nv_bfloat16* dst = &g_Acat[l][n0 + i][k0 + threadIdx.x];
        dst[0]     = h;
        dst[H]     = lo;
        dst[2 * H] = ll;
    }
}

// ---------------------------------------------------------------------------
// Convert W: [k 512][n 2048] fp32 -> [n][k] bf16, 6 blocks [h,l,ll,h,l,h]
// pairing x blocks [h,h,h,l,l,ll]
// ---------------------------------------------------------------------------
__global__ void convW_kernel(const float* __restrict__ W1, const float* __restrict__ W2)
{
    int l = blockIdx.z;
    const float* __restrict__ W = l ? W2 : W1;
    __shared__ float t[32][33];
    int k0 = blockIdx.x * 32, n0 = blockIdx.y * 32;
    for (int i = threadIdx.y; i < 32; i += 8)
        t[i][threadIdx.x] = W[(size_t)(k0 + i) * H + n0 + threadIdx.x];
    __syncthreads();
    for (int i = threadIdx.y; i < 32; i += 8) {
        float a = t[threadIdx.x][i];
        __nv_bfloat16 h, lo, ll;
        split3(a, h, lo, ll);
        __nv_bfloat16* dst = &g_Wcat[l][n0 + i][k0 + threadIdx.x];
        dst[0 * NIN] = h;
        dst[1 * NIN] = lo;
        dst[2 * NIN] = ll;
        dst[3 * NIN] = h;
        dst[4 * NIN] = lo;
        dst[5 * NIN] = h;
    }
}

// ---------------------------------------------------------------------------
// Convert x: x[b][t][k] fp32 -> g_xcat[t*64+b][ hi | lo | lolo ]
// ---------------------------------------------------------------------------
__global__ void convX_kernel(const float* __restrict__ x)
{
    int id = blockIdx.x * blockDim.x + threadIdx.x;
    if (id >= BATCH * FRAMES * NIN) return;
    int k = id & (NIN - 1);
    int row = id >> 9;                 // b*128 + t
    int b = row >> 7;
    int t = row & 127;
    float v = x[id];
    __nv_bfloat16 h, lo, ll;
    split3(v, h, lo, ll);
    __nv_bfloat16* dst = &g_xcat[t * BATCH + b][k];
    dst[0 * NIN] = h;
    dst[1 * NIN] = lo;
    dst[2 * NIN] = ll;
}

// ---------------------------------------------------------------------------
// Precompute U = x @ W + bias (fp32, per layer), split-bf16 mma with per-iter
// accumulator promotion. grid (128, 32, 2), 128 threads (4 warps, m32n32).
// ---------------------------------------------------------------------------
__global__ void __launch_bounds__(128)
precompU_kernel(const float* __restrict__ b1, const float* __restrict__ b2)
{
    const int l  = blockIdx.z;
    const int r0 = blockIdx.x * PBM;
    const int n0 = blockIdx.y * PBN;
    const float* __restrict__ bias = l ? b2 : b1;

    __shared__ __nv_bfloat16 smem[2][(PBM + PBN) * PSTR];   // ~36.9 KB

    const int tid  = threadIdx.x;
    const int lane = tid & 31;
    const int wid  = tid >> 5;
    const int wm   = wid & 1;    // m32 group
    const int wn   = wid >> 1;   // n32 group

    float acc[2][4][4];
    float mas[2][4][4];
#pragma unroll
    for (int i = 0; i < 2; i++)
#pragma unroll
        for (int j = 0; j < 4; j++)
#pragma unroll
            for (int r = 0; r < 4; r++) { acc[i][j][r] = 0.f; mas[i][j][r] = 0.f; }

    const int aRow = (lane & 7) + 8 * ((lane >> 3) & 1);
    const int aCol = 8 * (lane >> 4);
    const int bRow = (lane & 7) + 8 * (lane >> 4);
    const int bCol = 8 * ((lane >> 3) & 1);

    auto load_stage = [&](int it, int sidx) {
        __nv_bfloat16* sX = &smem[sidx][0];
        __nv_bfloat16* sW = &smem[sidx][PBM * PSTR];
        int k0 = it * PBK;
#pragma unroll
        for (int e = 0; e < 8; e++) {
            int idx = tid + e * 128;            // 0..1023
            if (idx < 512) {
                int row = idx >> 3, ch = idx & 7;
                int kk = k0 + ch * 8;
                int xb = (kk < 3 * NIN) ? 0 : ((kk < 5 * NIN) ? 1 : 2);
                cpasync16(sX + row * PSTR + ch * 8,
                          &g_xcat[r0 + row][xb * NIN + (kk & (NIN - 1))]);
            } else {
                int j = idx - 512;
                int row = j >> 3, ch = j & 7;
                cpasync16(sW + row * PSTR + ch * 8,
                          &g_Wcat[l][n0 + row][k0 + ch * 8]);
            }
        }
    };

    load_stage(0, 0); cp_commit();

    for (int it = 0; it < PNIT; it++) {
        if (it + 1 < PNIT) load_stage(it + 1, (it + 1) & 1);
        cp_commit();
        cp_wait1();
        __syncthreads();
        const __nv_bfloat16* sX = &smem[it & 1][0];
        const __nv_bfloat16* sW = &smem[it & 1][PBM * PSTR];
#pragma unroll
        for (int kq = 0; kq < PBK / 16; kq++) {
            uint32_t af[2][4];
            ldsm4(af[0], sX + (wm * 32 + aRow) * PSTR + kq * 16 + aCol);
            ldsm4(af[1], sX + (wm * 32 + 16 + aRow) * PSTR + kq * 16 + aCol);
            uint32_t bf0[4], bf1[4];
            ldsm4(bf0, sW + (wn * 32 + bRow) * PSTR + kq * 16 + bCol);
            ldsm4(bf1, sW + (wn * 32 + 16 + bRow) * PSTR + kq * 16 + bCol);
#pragma unroll
            for (int mr = 0; mr < 2; mr++) {
                mma16816(acc[mr][0], af[mr], bf0[0], bf0[1]);
                mma16816(acc[mr][1], af[mr], bf0[2], bf0[3]);
                mma16816(acc[mr][2], af[mr], bf1[0], bf1[1]);
                mma16816(acc[mr][3], af[mr], bf1[2], bf1[3]);
            }
        }
        // per-iteration promotion (kills mma RZ-bias chains)
#pragma unroll
        for (int i = 0; i < 2; i++)
#pragma unroll
            for (int j = 0; j < 4; j++)
#pragma unroll
                for (int r = 0; r < 4; r++) { mas[i][j][r] += acc[i][j][r]; acc[i][j][r] = 0.f; }
        __syncthreads();
    }

    // Epilogue: U = mas + bias
#pragma unroll
    for (int mr = 0; mr < 2; mr++)
#pragma unroll
        for (int nr = 0; nr < 4; nr++)
#pragma unroll
            for (int rr = 0; rr < 4; rr++) {
                int row = r0 + wm * 32 + mr * 16 + (lane >> 2) + 8 * (rr >> 1);
                int col = n0 + wn * 32 + nr * 8 + (lane & 3) * 2 + (rr & 1);
                g_U[l][row][col] = mas[mr][nr][rr] + bias[col];
            }
}

// ---------------------------------------------------------------------------
// Step kernel: z = s_prev @ (A hi+lo+lolo), K = 6144, split-K across warp
// groups, per-iter promotion + 2-level masters; LIF epilogue with precomputed U.
// grid (64, 2), 256 threads = 8 warps: wm(2) x wn(2) x wkg(2).
// ---------------------------------------------------------------------------
__global__ void __launch_bounds__(NTH, 1)
step_kernel(float* __restrict__ mems, float* __restrict__ spikes, int tt)
{
    const int l  = blockIdx.y;
    const int c0 = blockIdx.x * BN;

    __shared__ __nv_bfloat16 smem[STAGES][(BM + BN) * SSTR];   // 41.5 KB

    const int tid  = threadIdx.x;
    const int lane = tid & 31;
    const int wid  = tid >> 5;
    const int wm   = wid & 1;          // m32 group
    const int wn   = (wid >> 1) & 1;   // n16 group
    const int wkg  = wid >> 2;         // split-K group

    const __nv_bfloat16* __restrict__ sprev = &g_sbf[(tt - 1) & 1][l][0][0];
    const __nv_bfloat16* __restrict__ Acat  = &g_Acat[l][c0][0];

    auto load_stage = [&](int it, int sidx) {
        __nv_bfloat16* sS = &smem[sidx][0];
        __nv_bfloat16* sA = &smem[sidx][BM * SSTR];
        int k0 = it * BK;
#pragma unroll
        for (int e = 0; e < 3; e++) {
            int idx = tid + e * NTH;            // 0..767
            if (idx < 512) {
                int row = idx >> 3, ch = idx & 7;
                int ksrc = (k0 + ch * 8) & (H - 1);   // hi/lo/lolo blocks share s
                cpasync16(sS + row * SSTR + ch * 8, sprev + row * H + ksrc);
            } else {
                int j = idx - 512;
                int row = j >> 3, ch = j & 7;
                cpasync16(sA + row * SSTR + ch * 8,
                          Acat + (size_t)row * KA + k0 + ch * 8);
            }
        }
    };

    float acc[2][2][4], lvl1[2][2][4], lvl2[2][2][4];
#pragma unroll
    for (int i = 0; i < 2; i++)
#pragma unroll
        for (int j = 0; j < 2; j++)
#pragma unroll
            for (int r = 0; r < 4; r++) { acc[i][j][r] = 0.f; lvl1[i][j][r] = 0.f; lvl2[i][j][r] = 0.f; }

    const int aRow = (lane & 7) + 8 * ((lane >> 3) & 1);
    const int aCol = 8 * (lane >> 4);
    const int bRow = (lane & 7) + 8 * (lane >> 4);
    const int bCol = 8 * ((lane >> 3) & 1);

    load_stage(0, 0); cp_commit();
    load_stage(1, 1); cp_commit();

    for (int it = 0; it < NIT; it++) {
        cp_wait1();
        __syncthreads();
        const __nv_bfloat16* sS = &smem[it % STAGES][0];
        const __nv_bfloat16* sA = &smem[it % STAGES][BM * SSTR];
#pragma unroll
        for (int kk = 0; kk < 2; kk++) {
            const int kq = wkg * 2 + kk;        // this warp's K quarter-pair
            uint32_t af[2][4];
            ldsm4(af[0], sS + (wm * 32 + aRow) * SSTR + kq * 16 + aCol);
            ldsm4(af[1], sS + (wm * 32 + 16 + aRow) * SSTR + kq * 16 + aCol);
            uint32_t bf[4];
            ldsm4(bf, sA + (wn * 16 + bRow) * SSTR + kq * 16 + bCol);
#pragma unroll
            for (int mr = 0; mr < 2; mr++) {
                mma16816(acc[mr][0], af[mr], bf[0], bf[1]);
                mma16816(acc[mr][1], af[mr], bf[2], bf[3]);
            }
        }
        // per-iteration promotion into RN fp32 masters
#pragma unroll
        for (int i = 0; i < 2; i++)
#pragma unroll
            for (int j = 0; j < 2; j++)
#pragma unroll
                for (int r = 0; r < 4; r++) { lvl1[i][j][r] += acc[i][j][r]; acc[i][j][r] = 0.f; }
        if ((it & 7) == 7) {
#pragma unroll
            for (int i = 0; i < 2; i++)
#pragma unroll
                for (int j = 0; j < 2; j++)
#pragma unroll
                    for (int r = 0; r < 4; r++) { lvl2[i][j][r] += lvl1[i][j][r]; lvl1[i][j][r] = 0.f; }
        }
        if (it + 2 < NIT) load_stage(it + 2, (it + 2) % STAGES);
        cp_commit();
    }
#pragma unroll
    for (int i = 0; i < 2; i++)
#pragma unroll
        for (int j = 0; j < 2; j++)
#pragma unroll
            for (int r = 0; r < 4; r++) lvl2[i][j][r] += lvl1[i][j][r];

    // ---- split-K reduction through smem ----
    __syncthreads();
    float* red   = reinterpret_cast<float*>(&smem[0][0]);
    float* myred = red + (wid & 3) * 512 + lane * 16;
    if (wkg == 1) {
#pragma unroll
        for (int i = 0; i < 2; i++)
#pragma unroll
            for (int j = 0; j < 2; j++)
#pragma unroll
                for (int r = 0; r < 4; r++) myred[i * 8 + j * 4 + r] = lvl2[i][j][r];
    }
    __syncthreads();

    if (wkg == 0) {
        const int t = tt - 1;
        const size_t lay = (size_t)l * BATCH * TP1 * H;
        const float* __restrict__ Urow = &g_U[l][(size_t)t * BATCH][0];
#pragma unroll
        for (int mr = 0; mr < 2; mr++)
#pragma unroll
            for (int nr = 0; nr < 2; nr++)
#pragma unroll
                for (int r = 0; r < 4; r++) {
                    float z = lvl2[mr][nr][r] + myred[mr * 8 + nr * 4 + r];
                    int b   = wm * 32 + mr * 16 + (lane >> 2) + 8 * (r >> 1);
                    int col = c0 + wn * 16 + nr * 8 + (lane & 3) * 2 + (r & 1);
                    float u   = Urow[(size_t)b * H + col];
                    float pre = 0.5f * z + 0.5f * u;
                    float y   = tanhf(pre);
                    size_t ip = lay + ((size_t)b * TP1 + t) * H + col;
                    float sp = spikes[ip];
                    float mp = mems[ip];
                    float mn = mp * 0.5f - 0.5f * (1.0f - sp) + y;
                    mems[ip + H] = mn;
                    float sn = (mn > 0.5f) ? 1.0f : 0.0f;
                    spikes[ip + H] = sn;
                    g_sbf[tt & 1][l][b][col] = __float2bfloat16(sn);
                }
    }
}

// ---------------------------------------------------------------------------
// Launch
// ---------------------------------------------------------------------------
extern "C" void kernel_launch(void* const* d_in, const int* in_sizes, int n_in,
                              void* d_out, int out_size)
{
    const float* x   = (const float*)d_in[0];
    const float* W1  = (const float*)d_in[1];
    const float* A1  = (const float*)d_in[2];
    const float* b1  = (const float*)d_in[3];
    const float* W2  = (const float*)d_in[4];
    const float* A2  = (const float*)d_in[5];
    const float* b2  = (const float*)d_in[6];
    const float* m01 = (const float*)d_in[7];
    const float* m02 = (const float*)d_in[8];

    float* mems   = (float*)d_out;
    float* spikes = mems + (size_t)(out_size / 2);

    {
        int total = NL * BATCH * H;
        init_kernel<<<(total + 255) / 256, 256>>>(m01, m02, mems, spikes);
    }
    convA_kernel<<<dim3(H / 32, H / 32, NL), dim3(32, 8)>>>(A1, A2);
    convW_kernel<<<dim3(NIN / 32, H / 32, NL), dim3(32, 8)>>>(W1, W2);
    convX_kernel<<<(BATCH * FRAMES * NIN + 255) / 256, 256>>>(x);
    precompU_kernel<<<dim3(FRAMES * BATCH / PBM, H / PBN, NL), 128>>>(b1, b2);

    dim3 grid(H / BN, NL);   // 64 x 2 = 128 blocks
    for (int tt = 1; tt <= FRAMES; tt++) {
        step_kernel<<<grid, NTH>>>(mems, spikes, tt);
    }
}

// round 12
// speedup vs baseline: 3.5244x; 2.1627x over previous
#include <cuda_runtime.h>
#include <cuda_bf16.h>
#include <math.h>
#include <stdint.h>

// Problem constants
#define NL     2
#define BATCH  64
#define FRAMES 128
#define NIN    512
#define H      2048
#define TP1    129

#define KA   (3 * H)          // A splits (hi|lo|lolo) along k = 6144
#define KW   (6 * NIN)        // U GEMM K = 3072

// Step tiling: 64x32 block, 8 warps = 2m x 2n x 2kg(split-K); K over H with
// 3 A-parts per k-tile (s tile reused).
#define BM     64
#define BN     32
#define BK     64
#define HIT    (H / BK)       // 32 iters per step
#define NTH    256
#define SSTR   72             // padded smem row stride (bf16), conflict-free LDSM
#define STAGE_ELEMS ((BM + 3 * BN) * SSTR)   // 160*72 = 11520 bf16
#define SMEM_BYTES  (3 * STAGE_ELEMS * 2)    // 69120 B

// U-precompute tiling (unchanged, known-good)
#define PBM    64
#define PBN    64
#define PBK    64
#define PNIT   (KW / PBK)     // 48
#define PSTR   72

// ---------------------------------------------------------------------------
// Scratch (device globals)
// ---------------------------------------------------------------------------
__device__ __nv_bfloat16 g_Acat[NL][H][KA];               // [l][n][k] ~50 MB
__device__ __nv_bfloat16 g_Wcat[NL][H][KW];               // [l][n][k] ~25 MB
__device__ __nv_bfloat16 g_xcat[BATCH * FRAMES][3 * NIN]; // row=t*64+b ~25 MB
__device__ __nv_bfloat16 g_sbf[2][NL][BATCH][H];          // ping-pong spikes
__device__ float         g_U[NL][FRAMES * BATCH][H];      // U = xW + b ~134 MB

// Global barrier state for the persistent kernel
__device__ volatile unsigned g_genv = 0;
__device__ unsigned          g_cnt  = 0;

// ---------------------------------------------------------------------------
// Helpers
// ---------------------------------------------------------------------------
__device__ __forceinline__ void cpasync16(void* s, const void* g) {
    uint32_t sa = (uint32_t)__cvta_generic_to_shared(s);
    asm volatile("cp.async.cg.shared.global [%0], [%1], 16;\n" :: "r"(sa), "l"(g));
}
__device__ __forceinline__ void cp_commit() {
    asm volatile("cp.async.commit_group;\n" ::: "memory");
}
__device__ __forceinline__ void cp_wait1() {
    asm volatile("cp.async.wait_group 1;\n" ::: "memory");
}
__device__ __forceinline__ void ldsm4(uint32_t* r, const __nv_bfloat16* p) {
    uint32_t a = (uint32_t)__cvta_generic_to_shared(p);
    asm volatile("ldmatrix.sync.aligned.m8n8.x4.shared.b16 {%0,%1,%2,%3},[%4];"
                 : "=r"(r[0]), "=r"(r[1]), "=r"(r[2]), "=r"(r[3]) : "r"(a));
}
__device__ __forceinline__ void mma16816(float* c, const uint32_t* a, uint32_t b0, uint32_t b1) {
    asm volatile("mma.sync.aligned.m16n8k16.row.col.f32.bf16.bf16.f32 "
                 "{%0,%1,%2,%3},{%4,%5,%6,%7},{%8,%9},{%0,%1,%2,%3};"
                 : "+f"(c[0]), "+f"(c[1]), "+f"(c[2]), "+f"(c[3])
                 : "r"(a[0]), "r"(a[1]), "r"(a[2]), "r"(a[3]), "r"(b0), "r"(b1));
}
__device__ __forceinline__ void split3(float a, __nv_bfloat16& h, __nv_bfloat16& lo, __nv_bfloat16& ll) {
    h = __float2bfloat16(a);
    float r1 = a - __bfloat162float(h);
    lo = __float2bfloat16(r1);
    float r2 = r1 - __bfloat162float(lo);
    ll = __float2bfloat16(r2);
}

// ---------------------------------------------------------------------------
// Init: t=0 output slices + zero spike scratch (parity 0)
// ---------------------------------------------------------------------------
__global__ void init_kernel(const float* __restrict__ m01,
                            const float* __restrict__ m02,
                            float* __restrict__ mems,
                            float* __restrict__ spikes)
{
    int idx = blockIdx.x * blockDim.x + threadIdx.x;
    int total = NL * BATCH * H;
    if (idx >= total) return;
    int l = idx / (BATCH * H);
    int r = idx - l * (BATCH * H);
    int b = r / H;
    int h = r - b * H;
    const float* m0 = l ? m02 : m01;
    size_t o = (((size_t)l * BATCH + b) * TP1 + 0) * H + h;
    mems[o]   = m0[(size_t)b * H + h];
    spikes[o] = 0.0f;
    g_sbf[0][l][b][h] = __float2bfloat16(0.0f);
}

// ---------------------------------------------------------------------------
// Convert A: [k][n] fp32 -> [n][k] bf16 {hi, lo, lolo} at k, k+2048, k+4096
// ---------------------------------------------------------------------------
__global__ void convA_kernel(const float* __restrict__ A1, const float* __restrict__ A2)
{
    int l = blockIdx.z;
    const float* __restrict__ A = l ? A2 : A1;
    __shared__ float t[32][33];
    int k0 = blockIdx.x * 32, n0 = blockIdx.y * 32;
    for (int i = threadIdx.y; i < 32; i += 8)
        t[i][threadIdx.x] = A[(size_t)(k0 + i) * H + n0 + threadIdx.x];
    __syncthreads();
    for (int i = threadIdx.y; i < 32; i += 8) {
        float a = t[threadIdx.x][i];
        __nv_bfloat16 h, lo, ll;
        split3(a, h, lo, ll);
        __nv_bfloat16* dst = &g_Acat[l][n0 + i][k0 + threadIdx.x];
        dst[0]     = h;
        dst[H]     = lo;
        dst[2 * H] = ll;
    }
}

// ---------------------------------------------------------------------------
// Convert W: 6 blocks [h,l,ll,h,l,h] pairing x blocks [h,h,h,l,l,ll]
// ---------------------------------------------------------------------------
__global__ void convW_kernel(const float* __restrict__ W1, const float* __restrict__ W2)
{
    int l = blockIdx.z;
    const float* __restrict__ W = l ? W2 : W1;
    __shared__ float t[32][33];
    int k0 = blockIdx.x * 32, n0 = blockIdx.y * 32;
    for (int i = threadIdx.y; i < 32; i += 8)
        t[i][threadIdx.x] = W[(size_t)(k0 + i) * H + n0 + threadIdx.x];
    __syncthreads();
    for (int i = threadIdx.y; i < 32; i += 8) {
        float a = t[threadIdx.x][i];
        __nv_bfloat16 h, lo, ll;
        split3(a, h, lo, ll);
        __nv_bfloat16* dst = &g_Wcat[l][n0 + i][k0 + threadIdx.x];
        dst[0 * NIN] = h;
        dst[1 * NIN] = lo;
        dst[2 * NIN] = ll;
        dst[3 * NIN] = h;
        dst[4 * NIN] = lo;
        dst[5 * NIN] = h;
    }
}

// ---------------------------------------------------------------------------
// Convert x
// ---------------------------------------------------------------------------
__global__ void convX_kernel(const float* __restrict__ x)
{
    int id = blockIdx.x * blockDim.x + threadIdx.x;
    if (id >= BATCH * FRAMES * NIN) return;
    int k = id & (NIN - 1);
    int row = id >> 9;                 // b*128 + t
    int b = row >> 7;
    int t = row & 127;
    float v = x[id];
    __nv_bfloat16 h, lo, ll;
    split3(v, h, lo, ll);
    __nv_bfloat16* dst = &g_xcat[t * BATCH + b][k];
    dst[0 * NIN] = h;
    dst[1 * NIN] = lo;
    dst[2 * NIN] = ll;
}

// ---------------------------------------------------------------------------
// Precompute U = x @ W + bias (fp32) — unchanged from R10 (known-good)
// ---------------------------------------------------------------------------
__global__ void __launch_bounds__(128)
precompU_kernel(const float* __restrict__ b1, const float* __restrict__ b2)
{
    const int l  = blockIdx.z;
    const int r0 = blockIdx.x * PBM;
    const int n0 = blockIdx.y * PBN;
    const float* __restrict__ bias = l ? b2 : b1;

    __shared__ __nv_bfloat16 smem[2][(PBM + PBN) * PSTR];

    const int tid  = threadIdx.x;
    const int lane = tid & 31;
    const int wid  = tid >> 5;
    const int wm   = wid & 1;
    const int wn   = wid >> 1;

    float acc[2][4][4];
    float mas[2][4][4];
#pragma unroll
    for (int i = 0; i < 2; i++)
#pragma unroll
        for (int j = 0; j < 4; j++)
#pragma unroll
            for (int r = 0; r < 4; r++) { acc[i][j][r] = 0.f; mas[i][j][r] = 0.f; }

    const int aRow = (lane & 7) + 8 * ((lane >> 3) & 1);
    const int aCol = 8 * (lane >> 4);
    const int bRow = (lane & 7) + 8 * (lane >> 4);
    const int bCol = 8 * ((lane >> 3) & 1);

    auto load_stage = [&](int it, int sidx) {
        __nv_bfloat16* sX = &smem[sidx][0];
        __nv_bfloat16* sW = &smem[sidx][PBM * PSTR];
        int k0 = it * PBK;
#pragma unroll
        for (int e = 0; e < 8; e++) {
            int idx = tid + e * 128;
            if (idx < 512) {
                int row = idx >> 3, ch = idx & 7;
                int kk = k0 + ch * 8;
                int xb = (kk < 3 * NIN) ? 0 : ((kk < 5 * NIN) ? 1 : 2);
                cpasync16(sX + row * PSTR + ch * 8,
                          &g_xcat[r0 + row][xb * NIN + (kk & (NIN - 1))]);
            } else {
                int j = idx - 512;
                int row = j >> 3, ch = j & 7;
                cpasync16(sW + row * PSTR + ch * 8,
                          &g_Wcat[l][n0 + row][k0 + ch * 8]);
            }
        }
    };

    load_stage(0, 0); cp_commit();

    for (int it = 0; it < PNIT; it++) {
        if (it + 1 < PNIT) load_stage(it + 1, (it + 1) & 1);
        cp_commit();
        cp_wait1();
        __syncthreads();
        const __nv_bfloat16* sX = &smem[it & 1][0];
        const __nv_bfloat16* sW = &smem[it & 1][PBM * PSTR];
#pragma unroll
        for (int kq = 0; kq < PBK / 16; kq++) {
            uint32_t af[2][4];
            ldsm4(af[0], sX + (wm * 32 + aRow) * PSTR + kq * 16 + aCol);
            ldsm4(af[1], sX + (wm * 32 + 16 + aRow) * PSTR + kq * 16 + aCol);
            uint32_t bf0[4], bf1[4];
            ldsm4(bf0, sW + (wn * 32 + bRow) * PSTR + kq * 16 + bCol);
            ldsm4(bf1, sW + (wn * 32 + 16 + bRow) * PSTR + kq * 16 + bCol);
#pragma unroll
            for (int mr = 0; mr < 2; mr++) {
                mma16816(acc[mr][0], af[mr], bf0[0], bf0[1]);
                mma16816(acc[mr][1], af[mr], bf0[2], bf0[3]);
                mma16816(acc[mr][2], af[mr], bf1[0], bf1[1]);
                mma16816(acc[mr][3], af[mr], bf1[2], bf1[3]);
            }
        }
#pragma unroll
        for (int i = 0; i < 2; i++)
#pragma unroll
            for (int j = 0; j < 4; j++)
#pragma unroll
                for (int r = 0; r < 4; r++) { mas[i][j][r] += acc[i][j][r]; acc[i][j][r] = 0.f; }
        __syncthreads();
    }

#pragma unroll
    for (int mr = 0; mr < 2; mr++)
#pragma unroll
        for (int nr = 0; nr < 4; nr++)
#pragma unroll
            for (int rr = 0; rr < 4; rr++) {
                int row = r0 + wm * 32 + mr * 16 + (lane >> 2) + 8 * (rr >> 1);
                int col = n0 + wn * 32 + nr * 8 + (lane & 3) * 2 + (rr & 1);
                g_U[l][row][col] = mas[mr][nr][rr] + bias[col];
            }
}

// ---------------------------------------------------------------------------
// Persistent step kernel: ONE launch, loops tt = 1..128 with a global barrier.
// K iterates over H (32 iters); per iter the s tile is reused against 3 A-part
// tiles. grid = 128 blocks (64 n-tiles x 2 layers), 256 threads.
// ---------------------------------------------------------------------------
__global__ void __launch_bounds__(NTH, 1)
steps_persistent(float* __restrict__ mems, float* __restrict__ spikes)
{
    const int bid = blockIdx.x;
    const int l   = bid >> 6;
    const int c0  = (bid & 63) * BN;

    extern __shared__ __nv_bfloat16 dsm[];   // 3 * STAGE_ELEMS

    const int tid  = threadIdx.x;
    const int lane = tid & 31;
    const int wid  = tid >> 5;
    const int wm   = wid & 1;          // m32 group
    const int wn   = (wid >> 1) & 1;   // n16 group
    const int wkg  = wid >> 2;         // split-K group

    const __nv_bfloat16* __restrict__ Acat = &g_Acat[l][c0][0];

    const int aRow = (lane & 7) + 8 * ((lane >> 3) & 1);
    const int aCol = 8 * (lane >> 4);
    const int bRow = (lane & 7) + 8 * (lane >> 4);
    const int bCol = 8 * ((lane >> 3) & 1);

    unsigned gen0 = 0;
    if (tid == 0) gen0 = g_genv;       // stable: previous launch fully done

    for (int tt = 1; tt <= FRAMES; tt++) {
        const __nv_bfloat16* __restrict__ sprev = &g_sbf[(tt - 1) & 1][l][0][0];

        auto load_stage = [&](int it, int sidx) {
            __nv_bfloat16* st = dsm + sidx * STAGE_ELEMS;
            __nv_bfloat16* sS = st;
            __nv_bfloat16* sA = st + BM * SSTR;
            int k0 = it * BK;
#pragma unroll
            for (int e = 0; e < 5; e++) {
                int idx = tid + e * NTH;           // 0..1279
                if (idx < 512) {
                    int row = idx >> 3, ch = idx & 7;
                    cpasync16(sS + row * SSTR + ch * 8,
                              sprev + row * H + k0 + ch * 8);
                } else {
                    int j = idx - 512;             // 0..767
                    int p = j >> 8;                // part 0..2
                    int jr = j & 255;
                    int row = jr >> 3, ch = jr & 7;
                    cpasync16(sA + (p * 32 + row) * SSTR + ch * 8,
                              Acat + (size_t)row * KA + p * H + k0 + ch * 8);
                }
            }
        };

        float acc[2][2][4], lvl1[2][2][4], lvl2[2][2][4];
#pragma unroll
        for (int i = 0; i < 2; i++)
#pragma unroll
            for (int j = 0; j < 2; j++)
#pragma unroll
                for (int r = 0; r < 4; r++) { acc[i][j][r] = 0.f; lvl1[i][j][r] = 0.f; lvl2[i][j][r] = 0.f; }

        load_stage(0, 0); cp_commit();
        load_stage(1, 1); cp_commit();

        for (int it = 0; it < HIT; it++) {
            cp_wait1();
            __syncthreads();
            const __nv_bfloat16* st = dsm + (it % 3) * STAGE_ELEMS;
            const __nv_bfloat16* sS = st;
#pragma unroll
            for (int kk = 0; kk < 2; kk++) {
                const int kq = wkg * 2 + kk;
                uint32_t af[2][4];
                ldsm4(af[0], sS + (wm * 32 + aRow) * SSTR + kq * 16 + aCol);
                ldsm4(af[1], sS + (wm * 32 + 16 + aRow) * SSTR + kq * 16 + aCol);
#pragma unroll
                for (int p = 0; p < 3; p++) {
                    const __nv_bfloat16* sAp = st + (BM + p * 32) * SSTR;
                    uint32_t bf[4];
                    ldsm4(bf, sAp + (wn * 16 + bRow) * SSTR + kq * 16 + bCol);
#pragma unroll
                    for (int mr = 0; mr < 2; mr++) {
                        mma16816(acc[mr][0], af[mr], bf[0], bf[1]);
                        mma16816(acc[mr][1], af[mr], bf[2], bf[3]);
                    }
                }
            }
            // promote into RN fp32 masters (kills RZ chains)
#pragma unroll
            for (int i = 0; i < 2; i++)
#pragma unroll
                for (int j = 0; j < 2; j++)
#pragma unroll
                    for (int r = 0; r < 4; r++) { lvl1[i][j][r] += acc[i][j][r]; acc[i][j][r] = 0.f; }
            if ((it & 7) == 7) {
#pragma unroll
                for (int i = 0; i < 2; i++)
#pragma unroll
                    for (int j = 0; j < 2; j++)
#pragma unroll
                        for (int r = 0; r < 4; r++) { lvl2[i][j][r] += lvl1[i][j][r]; lvl1[i][j][r] = 0.f; }
            }
            if (it + 2 < HIT) load_stage(it + 2, (it + 2) % 3);
            cp_commit();
        }
#pragma unroll
        for (int i = 0; i < 2; i++)
#pragma unroll
            for (int j = 0; j < 2; j++)
#pragma unroll
                for (int r = 0; r < 4; r++) lvl2[i][j][r] += lvl1[i][j][r];

        // ---- split-K reduction through smem ----
        __syncthreads();
        float* red   = reinterpret_cast<float*>(dsm);
        float* myred = red + (wid & 3) * 512 + lane * 16;
        if (wkg == 1) {
#pragma unroll
            for (int i = 0; i < 2; i++)
#pragma unroll
                for (int j = 0; j < 2; j++)
#pragma unroll
                    for (int r = 0; r < 4; r++) myred[i * 8 + j * 4 + r] = lvl2[i][j][r];
        }
        __syncthreads();

        if (wkg == 0) {
            const int t = tt - 1;
            const size_t lay = (size_t)l * BATCH * TP1 * H;
            const float* __restrict__ Urow = &g_U[l][(size_t)t * BATCH][0];
#pragma unroll
            for (int mr = 0; mr < 2; mr++)
#pragma unroll
                for (int nr = 0; nr < 2; nr++)
#pragma unroll
                    for (int r = 0; r < 4; r++) {
                        float z = lvl2[mr][nr][r] + myred[mr * 8 + nr * 4 + r];
                        int b   = wm * 32 + mr * 16 + (lane >> 2) + 8 * (r >> 1);
                        int col = c0 + wn * 16 + nr * 8 + (lane & 3) * 2 + (r & 1);
                        float u   = Urow[(size_t)b * H + col];
                        float pre = 0.5f * z + 0.5f * u;
                        float y   = tanhf(pre);
                        size_t ip = lay + ((size_t)b * TP1 + t) * H + col;
                        float sp = spikes[ip];
                        float mp = mems[ip];
                        float mn = mp * 0.5f - 0.5f * (1.0f - sp) + y;
                        mems[ip + H] = mn;
                        float sn = (mn > 0.5f) ? 1.0f : 0.0f;
                        spikes[ip + H] = sn;
                        g_sbf[tt & 1][l][b][col] = __float2bfloat16(sn);
                    }
        }

        // ---- global barrier between steps ----
        if (tt < FRAMES) {
            __syncthreads();
            if (tid == 0) {
                __threadfence();
                unsigned my = gen0 + (unsigned)tt;
                if (atomicAdd(&g_cnt, 1) == (unsigned)(gridDim.x - 1)) {
                    g_cnt = 0;
                    __threadfence();
                    g_genv = my;
                } else {
                    while ((int)(g_genv - my) < 0) {}
                }
            }
            __syncthreads();
        }
    }
}

// ---------------------------------------------------------------------------
// Launch
// ---------------------------------------------------------------------------
extern "C" void kernel_launch(void* const* d_in, const int* in_sizes, int n_in,
                              void* d_out, int out_size)
{
    const float* x   = (const float*)d_in[0];
    const float* W1  = (const float*)d_in[1];
    const float* A1  = (const float*)d_in[2];
    const float* b1  = (const float*)d_in[3];
    const float* W2  = (const float*)d_in[4];
    const float* A2  = (const float*)d_in[5];
    const float* b2  = (const float*)d_in[6];
    const float* m01 = (const float*)d_in[7];
    const float* m02 = (const float*)d_in[8];

    float* mems   = (float*)d_out;
    float* spikes = mems + (size_t)(out_size / 2);

    static bool attr_done = false;
    if (!attr_done) {
        cudaFuncSetAttribute(steps_persistent,
                             cudaFuncAttributeMaxDynamicSharedMemorySize, SMEM_BYTES);
        attr_done = true;
    }

    {
        int total = NL * BATCH * H;
        init_kernel<<<(total + 255) / 256, 256>>>(m01, m02, mems, spikes);
    }
    convA_kernel<<<dim3(H / 32, H / 32, NL), dim3(32, 8)>>>(A1, A2);
    convW_kernel<<<dim3(NIN / 32, H / 32, NL), dim3(32, 8)>>>(W1, W2);
    convX_kernel<<<(BATCH * FRAMES * NIN + 255) / 256, 256>>>(x);
    precompU_kernel<<<dim3(FRAMES * BATCH / PBM, H / PBN, NL), 128>>>(b1, b2);

    steps_persistent<<<128, NTH, SMEM_BYTES>>>(mems, spikes);
}